// round 5
// baseline (speedup 1.0000x reference)
#include <cuda_runtime.h>
#include <cuda_bf16.h>

// NLL sequence loss: only the last valid timestep per batch row contributes.
//   loss = -(1/B) * sum_b inputs[b, min(T,length[b])-1, target[b]]
//
// 2 warps x 8 rows/thread. Index arrays read as 2x int4 per thread (one
// memory round); 8 independent gathers per thread overlap in one latency
// round. Reduction tail minimized: warp shuffles -> one smem word ->
// thread 0 adds and stores. Bench is floored at ~6.6-7.0us of graph-replay
// overhead; kernel body is ~0.3us warm.

#define B_DIM 512
#define T_DIM 128
#define C_DIM 2000
#define NTHREADS 64
#define RPT 8   // rows per thread = B_DIM / NTHREADS

__global__ __launch_bounds__(NTHREADS, 1)
void nll_seq_loss_kernel(const float* __restrict__ inputs,
                         const int*   __restrict__ length,
                         const int*   __restrict__ target,
                         float*       __restrict__ out) {
    const int t = threadIdx.x;
    const int base = t * RPT;   // contiguous 8-row chunk -> two aligned int4

    const int4* l4 = (const int4*)(length + base);
    const int4* g4 = (const int4*)(target + base);
    int4 l0 = l4[0], l1 = l4[1];
    int4 g0 = g4[0], g1 = g4[1];

    int len[RPT] = {l0.x, l0.y, l0.z, l0.w, l1.x, l1.y, l1.z, l1.w};
    int tgt[RPT] = {g0.x, g0.y, g0.z, g0.w, g1.x, g1.y, g1.z, g1.w};

    float v[RPT];
    #pragma unroll
    for (int j = 0; j < RPT; j++) {
        int last = (len[j] < T_DIM ? len[j] : T_DIM) - 1;
        int idx = ((base + j) * T_DIM + last) * C_DIM + tgt[j];
        v[j] = __ldg(inputs + idx);
    }

    // Pairwise in-register tree (shorter dependency chain than serial).
    float s01 = v[0] + v[1], s23 = v[2] + v[3];
    float s45 = v[4] + v[5], s67 = v[6] + v[7];
    float s = (s01 + s23) + (s45 + s67);

    #pragma unroll
    for (int off = 16; off > 0; off >>= 1)
        s += __shfl_down_sync(0xFFFFFFFFu, s, off);

    __shared__ float other;
    if (t == 32) other = s;     // warp 1 lane 0
    __syncthreads();

    if (t == 0)
        out[0] = -(s + other) * (1.0f / (float)B_DIM);
}

extern "C" void kernel_launch(void* const* d_in, const int* in_sizes, int n_in,
                              void* d_out, int out_size) {
    const float* inputs = (const float*)d_in[0];
    const int*   length = (const int*)d_in[1];
    const int*   target = (const int*)d_in[2];
    float*       out    = (float*)d_out;

    nll_seq_loss_kernel<<<1, NTHREADS>>>(inputs, length, target, out);
}

// round 6
// speedup vs baseline: 1.0048x; 1.0048x over previous
#include <cuda_runtime.h>
#include <cuda_bf16.h>

// NLL sequence loss: only the last valid timestep per batch row contributes.
//   loss = -(1/B) * sum_b inputs[b, min(T,length[b])-1, target[b]]
//
// Converged form. 4 warps x 4 rows/thread:
//  - length/target read as one int4 per array per thread (one memory round).
//  - 4 independent gathers per thread; all 512 gathers overlap in a single
//    L2/DRAM latency round chip-wide.
//  - Reduction: 3 register adds -> 5 warp shuffles -> 4 smem words -> one
//    thread does 3 adds + store (no second shuffle cascade).
// Measured bench time (~6.6-6.7us) is graph-replay/launch overhead; the warm
// kernel body is ~0.3-0.4us and cannot be reduced further (gather is a
// dependent two-load chain by construction).

#define B_DIM 512
#define T_DIM 128
#define C_DIM 2000
#define NTHREADS 128
#define RPT 4   // rows per thread = B_DIM / NTHREADS
#define NWARPS (NTHREADS / 32)

__global__ __launch_bounds__(NTHREADS, 1)
void nll_seq_loss_kernel(const float* __restrict__ inputs,
                         const int*   __restrict__ length,
                         const int*   __restrict__ target,
                         float*       __restrict__ out) {
    const int t = threadIdx.x;
    const int base = t * RPT;   // contiguous 4-row chunk -> aligned int4

    int4 l = *(const int4*)(length + base);
    int4 g = *(const int4*)(target + base);

    int len[RPT] = {l.x, l.y, l.z, l.w};
    int tgt[RPT] = {g.x, g.y, g.z, g.w};

    float v[RPT];
    #pragma unroll
    for (int j = 0; j < RPT; j++) {
        int last = (len[j] < T_DIM ? len[j] : T_DIM) - 1;
        int idx = ((base + j) * T_DIM + last) * C_DIM + tgt[j];
        v[j] = __ldg(inputs + idx);
    }

    float s = (v[0] + v[1]) + (v[2] + v[3]);

    #pragma unroll
    for (int off = 16; off > 0; off >>= 1)
        s += __shfl_down_sync(0xFFFFFFFFu, s, off);

    __shared__ float warp_sums[NWARPS];
    const int lane = t & 31;
    const int wid  = t >> 5;
    if (lane == 0) warp_sums[wid] = s;
    __syncthreads();

    if (t == 0) {
        float w = (warp_sums[0] + warp_sums[1]) + (warp_sums[2] + warp_sums[3]);
        out[0] = w * (-1.0f / (float)B_DIM);
    }
}

extern "C" void kernel_launch(void* const* d_in, const int* in_sizes, int n_in,
                              void* d_out, int out_size) {
    const float* inputs = (const float*)d_in[0];
    const int*   length = (const int*)d_in[1];
    const int*   target = (const int*)d_in[2];
    float*       out    = (float*)d_out;

    nll_seq_loss_kernel<<<1, NTHREADS>>>(inputs, length, target, out);
}